// round 14
// baseline (speedup 1.0000x reference)
#include <cuda_runtime.h>
#include <cuda_fp16.h>
#include <cstdint>

// Problem constants
#define NROWS 65536
#define DIM   256
#define NE    8192

// Output packing (float32, reference return order)
#define XQ_OFF   0ULL
#define LOSS_OFF 16777216ULL
#define IDX_OFF  16777217ULL
#define D_OFF    16842753ULL

// ---------------------------------------------------------------------------
// Device scratch
// ---------------------------------------------------------------------------
__device__ uint4 g_xh[NROWS * 32];   // fp16 x rows (32MB)
__device__ uint4 g_eh[NE * 32];      // fp16 emb rows, pre-scaled by 4096 (4MB)
__device__ __align__(16) float g_xnorm[NROWS];
__device__ __align__(16) float g_enorm[NE];
__device__ int    g_cand[NROWS * 32];   // 32 argmin candidates per row (8MB)
__device__ double g_losssum;

// ---------------------------------------------------------------------------
// helpers
// ---------------------------------------------------------------------------
__device__ __forceinline__ uint32_t smem_to_u32(const void* p) {
    uint32_t a;
    asm("{ .reg .u64 t; cvta.to.shared.u64 t, %1; cvt.u32.u64 %0, t; }"
        : "=r"(a) : "l"(p));
    return a;
}
__device__ __forceinline__ uint64_t to_global(const void* p) {
    uint64_t g;
    asm("cvta.to.global.u64 %0, %1;" : "=l"(g) : "l"(p));
    return g;
}
#define CP_ASYNC_16(dst, src) \
    asm volatile("cp.async.cg.shared.global [%0], [%1], 16;" :: "r"(dst), "l"(src))
#define CP_COMMIT() asm volatile("cp.async.commit_group;" ::: "memory")
#define CP_WAIT(n)  asm volatile("cp.async.wait_group %0;" :: "n"(n) : "memory")

#define LDMATRIX_X4(r, addr) \
    asm volatile("ldmatrix.sync.aligned.m8n8.x4.shared.b16 {%0,%1,%2,%3}, [%4];" \
        : "=r"((r)[0]), "=r"((r)[1]), "=r"((r)[2]), "=r"((r)[3]) : "r"(addr))

// fp16-accumulate HMMA: C fragment = 2 regs (half2 per 8-row block)
#define MMA_16816_H(c, a, b0, b1) \
    asm volatile("mma.sync.aligned.m16n8k16.row.col.f16.f16.f16.f16 " \
        "{%0,%1}, {%2,%3,%4,%5}, {%6,%7}, {%0,%1};" \
        : "+r"((c)[0]), "+r"((c)[1]) \
        : "r"((a)[0]), "r"((a)[1]), "r"((a)[2]), "r"((a)[3]), "r"(b0), "r"(b1))

__device__ __forceinline__ uint32_t pack_half2(__half lo, __half hi) {
    return (uint32_t)__half_as_ushort(lo) | ((uint32_t)__half_as_ushort(hi) << 16);
}

// ---------------------------------------------------------------------------
// prep+norms fused: one warp per row. Norm reduction is bitwise-identical to
// the validated vq_norms; fp16 split conversion reuses the same row read.
// ---------------------------------------------------------------------------
__global__ void __launch_bounds__(256) vq_prep(const float* __restrict__ x,
                                               const float* __restrict__ emb) {
    if (blockIdx.x == 0 && threadIdx.x == 0) g_losssum = 0.0;
    int warp = threadIdx.x >> 5;
    int lane = threadIdx.x & 31;
    int row = blockIdx.x * 8 + warp;
    const float* src;
    float* ndst;
    uint4* qdst;
    float sc;
    if (row < NE) {
        src = emb + (size_t)row * DIM; ndst = g_enorm + row;
        qdst = g_eh + (size_t)row * 32; sc = 4096.0f;
    } else {
        int r = row - NE;
        if (r >= NROWS) return;
        src = x + (size_t)r * DIM; ndst = g_xnorm + r;
        qdst = g_xh + (size_t)r * 32; sc = 1.0f;
    }
    const float4* p = (const float4*)src;
    float4 v0 = p[lane * 2];
    float4 v1 = p[lane * 2 + 1];
    float s = v0.x*v0.x + v0.y*v0.y + v0.z*v0.z + v0.w*v0.w
            + v1.x*v1.x + v1.y*v1.y + v1.z*v1.z + v1.w*v1.w;
    #pragma unroll
    for (int o = 16; o > 0; o >>= 1)
        s += __shfl_down_sync(0xffffffffu, s, o);
    if (lane == 0) *ndst = s;

    __half h[8];
    h[0] = __float2half_rn(v0.x * sc); h[1] = __float2half_rn(v0.y * sc);
    h[2] = __float2half_rn(v0.z * sc); h[3] = __float2half_rn(v0.w * sc);
    h[4] = __float2half_rn(v1.x * sc); h[5] = __float2half_rn(v1.y * sc);
    h[6] = __float2half_rn(v1.z * sc); h[7] = __float2half_rn(v1.w * sc);
    uint4 u;
    u.x = pack_half2(h[0], h[1]); u.y = pack_half2(h[2], h[3]);
    u.z = pack_half2(h[4], h[5]); u.w = pack_half2(h[6], h[7]);
    qdst[lane * 2 / 2] = u;   // one uint4 per lane? no: lane covers 8 halves = 1 uint4
}

// ---------------------------------------------------------------------------
// Main HMMA kernel: BM=64 (fine-grain scheduling), K=256 fp16, fp16 acc,
// occupancy 2, paired float2 streaming stores, per-lane top-2 candidates
// (16 lane-slots per row -> 32 candidates).
// ---------------------------------------------------------------------------
#define BM 64
#define BN 128
#define NCH 4
#define NT  (NE / BN)          // 64
#define NQ  (NT * NCH)         // 256
#define SM_A 0
#define SM_B 32768
#define SMEM_TOTAL 81920       // 32KB A + 3*16KB B (x2 CTAs = 160KB)

__global__ void __launch_bounds__(256, 2) vq_main_mma(float* __restrict__ out) {
    extern __shared__ char smem[];
    const uint32_t smem_u32 = smem_to_u32(smem);
    const uint32_t Ab = smem_u32 + SM_A;
    const int tid = threadIdx.x;
    const int lane = tid & 31;
    const int wid = tid >> 5;
    const int wm = wid & 1;          // 2 m-warps x 32 rows
    const int wn = wid >> 1;         // 4 n-warps x 32 cols
    const int g = lane >> 2;
    const int t = lane & 3;
    const int m0 = blockIdx.x * BM;

    const uint64_t xh_g = to_global(g_xh);
    const uint64_t eh_g = to_global(g_eh);

    // A load: 64 rows x 32 16B-chunks (32KB)
    #pragma unroll
    for (int i = 0; i < 8; i++) {
        int idx = tid + i * 256;
        int row = idx >> 5;
        int ch  = idx & 31;
        uint64_t src = xh_g + (((uint64_t)(m0 + row)) * 32 + ch) * 16;
        uint32_t dst = Ab + row * 512 + ((ch ^ (row & 7)) << 4);
        CP_ASYNC_16(dst, src);
    }
    CP_COMMIT();

    // B prologue: chunks 0,1 into stages 0,1
    #pragma unroll
    for (int p = 0; p < 2; p++) {
        uint32_t dstb = smem_u32 + SM_B + p * 16384;
        #pragma unroll
        for (int i = 0; i < 4; i++) {
            int idx = tid + i * 256;
            int row = idx >> 3;
            int ch  = idx & 7;
            uint64_t src = eh_g + (((uint64_t)row) * 32 + p * 8 + ch) * 16;
            uint32_t dst = dstb + row * 128 + ((ch ^ (row & 7)) << 4);
            CP_ASYNC_16(dst, src);
        }
        CP_COMMIT();
    }

    float xnv[4];
    #pragma unroll
    for (int ii = 0; ii < 4; ii++)
        xnv[ii] = g_xnorm[m0 + wm * 32 + (ii >> 1) * 16 + (ii & 1) * 8 + g];
    float mv1[4] = {3.4e38f, 3.4e38f, 3.4e38f, 3.4e38f};
    float mv2[4] = {3.4e38f, 3.4e38f, 3.4e38f, 3.4e38f};
    int   mi1[4] = {0, 0, 0, 0};
    int   mi2[4] = {0, 0, 0, 0};

    int q = 0;
    int sfill = 2, suse = 0;
    for (int n = 0; n < NT; n++) {
        const int n0 = n * BN;
        uint32_t acc[2][4][2];
        #pragma unroll
        for (int i = 0; i < 2; i++)
            #pragma unroll
            for (int j = 0; j < 4; j++) {
                acc[i][j][0] = 0u; acc[i][j][1] = 0u;
            }

        #pragma unroll
        for (int c = 0; c < NCH; c++, q++) {
            CP_WAIT(1);
            __syncthreads();

            int qi = q + 2;
            if (qi < NQ) {
                int nn = qi >> 2, cc = qi & 3;
                uint32_t dstb = smem_u32 + SM_B + sfill * 16384;
                #pragma unroll
                for (int i = 0; i < 4; i++) {
                    int idx = tid + i * 256;
                    int row = idx >> 3;
                    int ch  = idx & 7;
                    uint64_t src = eh_g + (((uint64_t)(nn * BN + row)) * 32 + cc * 8 + ch) * 16;
                    uint32_t dst = dstb + row * 128 + ((ch ^ (row & 7)) << 4);
                    CP_ASYNC_16(dst, src);
                }
            }
            CP_COMMIT();
            sfill++; if (sfill == 3) sfill = 0;

            const uint32_t Bb = smem_u32 + SM_B + suse * 16384;
            suse++; if (suse == 3) suse = 0;
            const int aK = c * 8;
            #pragma unroll
            for (int ks = 0; ks < 4; ks++) {
                uint32_t a[2][4];
                #pragma unroll
                for (int i = 0; i < 2; i++) {
                    int row = wm * 32 + i * 16 + (lane & 15);
                    int ch = aK + ks * 2 + (lane >> 4);
                    LDMATRIX_X4(a[i], Ab + row * 512 + ((ch ^ (row & 7)) << 4));
                }
                #pragma unroll
                for (int jj = 0; jj < 2; jj++) {
                    uint32_t b[4];
                    int nloc = wn * 32 + jj * 16 + (lane & 7) + ((lane >> 4) << 3);
                    int ch = ks * 2 + ((lane >> 3) & 1);
                    LDMATRIX_X4(b, Bb + nloc * 128 + ((ch ^ (nloc & 7)) << 4));
                    #pragma unroll
                    for (int i = 0; i < 2; i++) {
                        MMA_16816_H(acc[i][jj * 2],     a[i], b[0], b[1]);
                        MMA_16816_H(acc[i][jj * 2 + 1], a[i], b[2], b[3]);
                    }
                }
            }
        }

        // ---- epilogue: unpack fp16 acc, paired stores, top-2 tracking ----
        const float* enb = g_enorm + n0 + wn * 32 + 2 * t;
        #pragma unroll
        for (int i = 0; i < 2; i++) {
            #pragma unroll
            for (int p = 0; p < 2; p++) {
                const int ii = i * 2 + p;
                const int grow = m0 + wm * 32 + i * 16 + p * 8 + g;
                const float xnr = xnv[ii];
                float* drow = out + D_OFF + (size_t)grow * NE + n0 + wn * 32;
                float prev_d1 = 0.0f;
                #pragma unroll
                for (int j = 0; j < 4; j++) {
                    float2 e2 = *(const float2*)(enb + j * 8);
                    float2 Sv = __half22float2(*(const __half2*)&acc[i][j][p]);
                    float d0 = fmaf(Sv.x, -4.8828125e-4f, xnr + e2.x);
                    float d1 = fmaf(Sv.y, -4.8828125e-4f, xnr + e2.y);
                    int cidx = n0 + wn * 32 + j * 8 + 2 * t;
                    if (d0 < mv2[ii]) {
                        if (d0 < mv1[ii]) { mv2[ii]=mv1[ii]; mi2[ii]=mi1[ii];
                                            mv1[ii]=d0; mi1[ii]=cidx; }
                        else { mv2[ii]=d0; mi2[ii]=cidx; }
                    }
                    if (d1 < mv2[ii]) {
                        if (d1 < mv1[ii]) { mv2[ii]=mv1[ii]; mi2[ii]=mi1[ii];
                                            mv1[ii]=d1; mi1[ii]=cidx+1; }
                        else { mv2[ii]=d1; mi2[ii]=cidx+1; }
                    }
                    float rot = __shfl_sync(0xffffffffu, d0, t + 1, 4);
                    if (t < 3) {
                        float2 v = make_float2(d1, rot);
                        __stcs((float2*)(drow + j * 8 + 2 * t + 1), v);
                    } else if (j > 0) {
                        float2 v = make_float2(prev_d1, rot);
                        __stcs((float2*)(drow + (j - 1) * 8 + 7), v);
                    }
                    if (t == 0 && j == 0) __stcs(drow, d0);
                    prev_d1 = d1;
                }
                if (t == 3) __stcs(drow + 31, prev_d1);
            }
        }
    }

    // dump per-lane top-2 candidates (16 lane-slots per row x 2 = 32 per row)
    #pragma unroll
    for (int ii = 0; ii < 4; ii++) {
        int grow = m0 + wm * 32 + (ii >> 1) * 16 + (ii & 1) * 8 + g;
        int base = grow * 32 + (wn * 4 + t) * 2;
        g_cand[base]     = mi1[ii];
        g_cand[base + 1] = mi2[ii];
    }
}

// ---------------------------------------------------------------------------
// Refine + gather + loss (fused). One warp per row, 32 candidates,
// coalesced emb loads, exact fp32 arithmetic (validated).
// ---------------------------------------------------------------------------
__global__ void __launch_bounds__(256) vq_refine(const float* __restrict__ x,
                                                 const float* __restrict__ emb,
                                                 float* __restrict__ out) {
    __shared__ double sd[8];
    const int warp = threadIdx.x >> 5;
    const int lane = threadIdx.x & 31;
    const int row = blockIdx.x * 8 + warp;

    const float4* xp = (const float4*)(x + (size_t)row * DIM);
    const float4 xa = xp[lane];
    const float4 xb = xp[lane + 32];
    const float xn = g_xnorm[row];

    float bv = 3.4e38f;
    int bi = 0x7fffffff;
    #pragma unroll 4
    for (int c = 0; c < 32; c++) {
        const int idx = g_cand[row * 32 + c];
        const float4* ep = (const float4*)(emb + (size_t)idx * DIM);
        float4 ea = __ldg(ep + lane);
        float4 eb = __ldg(ep + lane + 32);
        float s = xa.x * ea.x;
        s = __fmaf_rn(xa.y, ea.y, s);
        s = __fmaf_rn(xa.z, ea.z, s);
        s = __fmaf_rn(xa.w, ea.w, s);
        s = __fmaf_rn(xb.x, eb.x, s);
        s = __fmaf_rn(xb.y, eb.y, s);
        s = __fmaf_rn(xb.z, eb.z, s);
        s = __fmaf_rn(xb.w, eb.w, s);
        #pragma unroll
        for (int o = 16; o > 0; o >>= 1)
            s += __shfl_xor_sync(0xffffffffu, s, o);
        float dv = __fmaf_rn(-2.0f, s, __fadd_rn(xn, g_enorm[idx]));
        if (dv < bv || (dv == bv && idx < bi)) { bv = dv; bi = idx; }
    }
    if (lane == 0) out[IDX_OFF + row] = (float)bi;

    const float4* ep = (const float4*)(emb + (size_t)bi * DIM);
    float4 ea = __ldg(ep + lane);
    float4 eb = __ldg(ep + lane + 32);
    float4 o1, o2;
    float dax = ea.x - xa.x, day = ea.y - xa.y, daz = ea.z - xa.z, daw = ea.w - xa.w;
    float dbx = eb.x - xb.x, dby = eb.y - xb.y, dbz = eb.z - xb.z, dbw = eb.w - xb.w;
    o1.x = xa.x + dax; o1.y = xa.y + day; o1.z = xa.z + daz; o1.w = xa.w + daw;
    o2.x = xb.x + dbx; o2.y = xb.y + dby; o2.z = xb.z + dbz; o2.w = xb.w + dbw;
    float4* oq = (float4*)(out + XQ_OFF + (size_t)row * DIM);
    oq[lane] = o1;
    oq[lane + 32] = o2;

    float s2 = dax*dax + day*day + daz*daz + daw*daw
             + dbx*dbx + dby*dby + dbz*dbz + dbw*dbw;
    #pragma unroll
    for (int o = 16; o > 0; o >>= 1)
        s2 += __shfl_down_sync(0xffffffffu, s2, o);
    if (lane == 0) sd[warp] = (double)s2;
    __syncthreads();
    if (threadIdx.x == 0) {
        double bs = 0.0;
        #pragma unroll
        for (int w = 0; w < 8; w++) bs += sd[w];
        atomicAdd(&g_losssum, bs);
    }
}

__global__ void vq_loss(float* __restrict__ out) {
    double mse = g_losssum / (double)(NROWS * DIM);
    out[LOSS_OFF] = (float)(1.25 * mse);
}

// ---------------------------------------------------------------------------
extern "C" void kernel_launch(void* const* d_in, const int* in_sizes, int n_in,
                              void* d_out, int out_size) {
    const float* x = (const float*)d_in[0];
    const float* emb = (const float*)d_in[1];
    float* out = (float*)d_out;
    (void)in_sizes; (void)n_in; (void)out_size;

    static bool attr_set = false;
    if (!attr_set) {
        cudaFuncSetAttribute(vq_main_mma, cudaFuncAttributeMaxDynamicSharedMemorySize,
                             SMEM_TOTAL);
        attr_set = true;
    }

    vq_prep<<<(NE + NROWS) / 8, 256>>>(x, emb);
    vq_main_mma<<<NROWS / BM, 256, SMEM_TOTAL>>>(out);
    vq_refine<<<NROWS / 8, 256>>>(x, emb, out);
    vq_loss<<<1, 1>>>(out);
}

// round 15
// speedup vs baseline: 1.0394x; 1.0394x over previous
#include <cuda_runtime.h>
#include <cuda_fp16.h>
#include <cstdint>

// Problem constants
#define NROWS 65536
#define DIM   256
#define NE    8192

// Output packing (float32, reference return order)
#define XQ_OFF   0ULL
#define LOSS_OFF 16777216ULL
#define IDX_OFF  16777217ULL
#define D_OFF    16842753ULL

// ---------------------------------------------------------------------------
// Device scratch
// ---------------------------------------------------------------------------
__device__ uint4 g_xh[NROWS * 32];   // fp16 x rows (32MB)
__device__ uint4 g_eh[NE * 32];      // fp16 emb rows, pre-scaled by 4096 (4MB)
__device__ __align__(16) float g_xnorm[NROWS];
__device__ __align__(16) float g_enorm[NE];
__device__ int    g_cand[NROWS * 24];   // 24 argmin candidates per row (6MB)
__device__ double g_losssum;

// ---------------------------------------------------------------------------
// helpers
// ---------------------------------------------------------------------------
__device__ __forceinline__ uint32_t smem_to_u32(const void* p) {
    uint32_t a;
    asm("{ .reg .u64 t; cvta.to.shared.u64 t, %1; cvt.u32.u64 %0, t; }"
        : "=r"(a) : "l"(p));
    return a;
}
__device__ __forceinline__ uint64_t to_global(const void* p) {
    uint64_t g;
    asm("cvta.to.global.u64 %0, %1;" : "=l"(g) : "l"(p));
    return g;
}
#define CP_ASYNC_16(dst, src) \
    asm volatile("cp.async.cg.shared.global [%0], [%1], 16;" :: "r"(dst), "l"(src))
#define CP_COMMIT() asm volatile("cp.async.commit_group;" ::: "memory")
#define CP_WAIT(n)  asm volatile("cp.async.wait_group %0;" :: "n"(n) : "memory")

#define LDMATRIX_X4(r, addr) \
    asm volatile("ldmatrix.sync.aligned.m8n8.x4.shared.b16 {%0,%1,%2,%3}, [%4];" \
        : "=r"((r)[0]), "=r"((r)[1]), "=r"((r)[2]), "=r"((r)[3]) : "r"(addr))

// fp16-accumulate HMMA: C fragment = 2 regs (half2 per 8-row block)
#define MMA_16816_H(c, a, b0, b1) \
    asm volatile("mma.sync.aligned.m16n8k16.row.col.f16.f16.f16.f16 " \
        "{%0,%1}, {%2,%3,%4,%5}, {%6,%7}, {%0,%1};" \
        : "+r"((c)[0]), "+r"((c)[1]) \
        : "r"((a)[0]), "r"((a)[1]), "r"((a)[2]), "r"((a)[3]), "r"(b0), "r"(b1))

__device__ __forceinline__ uint32_t pack_half2(__half lo, __half hi) {
    return (uint32_t)__half_as_ushort(lo) | ((uint32_t)__half_as_ushort(hi) << 16);
}

// ---------------------------------------------------------------------------
// prep+norms fused: one warp per row, single read of the source row.
// Norm reduction is bitwise-identical to the validated vq_norms.
// ---------------------------------------------------------------------------
__global__ void __launch_bounds__(256) vq_prep(const float* __restrict__ x,
                                               const float* __restrict__ emb) {
    if (blockIdx.x == 0 && threadIdx.x == 0) g_losssum = 0.0;
    int warp = threadIdx.x >> 5;
    int lane = threadIdx.x & 31;
    int row = blockIdx.x * 8 + warp;
    const float* src;
    float* ndst;
    uint4* qdst;
    float sc;
    if (row < NE) {
        src = emb + (size_t)row * DIM; ndst = g_enorm + row;
        qdst = g_eh + (size_t)row * 32; sc = 4096.0f;
    } else {
        int r = row - NE;
        if (r >= NROWS) return;
        src = x + (size_t)r * DIM; ndst = g_xnorm + r;
        qdst = g_xh + (size_t)r * 32; sc = 1.0f;
    }
    const float4* p = (const float4*)src;
    float4 v0 = p[lane * 2];
    float4 v1 = p[lane * 2 + 1];
    float s = v0.x*v0.x + v0.y*v0.y + v0.z*v0.z + v0.w*v0.w
            + v1.x*v1.x + v1.y*v1.y + v1.z*v1.z + v1.w*v1.w;
    #pragma unroll
    for (int o = 16; o > 0; o >>= 1)
        s += __shfl_down_sync(0xffffffffu, s, o);
    if (lane == 0) *ndst = s;

    __half h[8];
    h[0] = __float2half_rn(v0.x * sc); h[1] = __float2half_rn(v0.y * sc);
    h[2] = __float2half_rn(v0.z * sc); h[3] = __float2half_rn(v0.w * sc);
    h[4] = __float2half_rn(v1.x * sc); h[5] = __float2half_rn(v1.y * sc);
    h[6] = __float2half_rn(v1.z * sc); h[7] = __float2half_rn(v1.w * sc);
    uint4 u;
    u.x = pack_half2(h[0], h[1]); u.y = pack_half2(h[2], h[3]);
    u.z = pack_half2(h[4], h[5]); u.w = pack_half2(h[6], h[7]);
    qdst[lane] = u;
}

// ---------------------------------------------------------------------------
// Main HMMA kernel: BM=128, K=256 fp16, fp16 acc, occupancy 2,
// paired float2 streaming stores, per-lane top-3 candidates. (r12 verbatim)
// ---------------------------------------------------------------------------
#define BM 128
#define BN 128
#define NCH 4
#define NT  (NE / BN)          // 64
#define NQ  (NT * NCH)         // 256
#define SM_A 0
#define SM_B 65536
#define SMEM_TOTAL 114688      // 64KB A + 3*16KB B (x2 CTAs = 224KB)

__global__ void __launch_bounds__(256, 2) vq_main_mma(float* __restrict__ out) {
    extern __shared__ char smem[];
    const uint32_t smem_u32 = smem_to_u32(smem);
    const uint32_t Ab = smem_u32 + SM_A;
    const int tid = threadIdx.x;
    const int lane = tid & 31;
    const int wid = tid >> 5;
    const int wm = wid & 3;
    const int wn = wid >> 2;
    const int g = lane >> 2;
    const int t = lane & 3;
    const int m0 = blockIdx.x * BM;

    const uint64_t xh_g = to_global(g_xh);
    const uint64_t eh_g = to_global(g_eh);

    // A load: 128 rows x 32 16B-chunks
    #pragma unroll
    for (int i = 0; i < 16; i++) {
        int idx = tid + i * 256;
        int row = idx >> 5;
        int ch  = idx & 31;
        uint64_t src = xh_g + (((uint64_t)(m0 + row)) * 32 + ch) * 16;
        uint32_t dst = Ab + row * 512 + ((ch ^ (row & 7)) << 4);
        CP_ASYNC_16(dst, src);
    }
    CP_COMMIT();

    // B prologue: chunks 0,1 into stages 0,1
    #pragma unroll
    for (int p = 0; p < 2; p++) {
        uint32_t dstb = smem_u32 + SM_B + p * 16384;
        #pragma unroll
        for (int i = 0; i < 4; i++) {
            int idx = tid + i * 256;
            int row = idx >> 3;
            int ch  = idx & 7;
            uint64_t src = eh_g + (((uint64_t)row) * 32 + p * 8 + ch) * 16;
            uint32_t dst = dstb + row * 128 + ((ch ^ (row & 7)) << 4);
            CP_ASYNC_16(dst, src);
        }
        CP_COMMIT();
    }

    float xnv[4];
    #pragma unroll
    for (int ii = 0; ii < 4; ii++)
        xnv[ii] = g_xnorm[m0 + wm * 32 + (ii >> 1) * 16 + (ii & 1) * 8 + g];
    float mv1[4] = {3.4e38f, 3.4e38f, 3.4e38f, 3.4e38f};
    float mv2[4] = {3.4e38f, 3.4e38f, 3.4e38f, 3.4e38f};
    float mv3[4] = {3.4e38f, 3.4e38f, 3.4e38f, 3.4e38f};
    int   mi1[4] = {0,0,0,0}, mi2[4] = {0,0,0,0}, mi3[4] = {0,0,0,0};

    int q = 0;
    int sfill = 2, suse = 0;
    for (int n = 0; n < NT; n++) {
        const int n0 = n * BN;
        uint32_t acc[2][8][2];
        #pragma unroll
        for (int i = 0; i < 2; i++)
            #pragma unroll
            for (int j = 0; j < 8; j++) {
                acc[i][j][0] = 0u; acc[i][j][1] = 0u;
            }

        #pragma unroll
        for (int c = 0; c < NCH; c++, q++) {
            CP_WAIT(1);
            __syncthreads();

            int qi = q + 2;
            if (qi < NQ) {
                int nn = qi >> 2, cc = qi & 3;
                uint32_t dstb = smem_u32 + SM_B + sfill * 16384;
                #pragma unroll
                for (int i = 0; i < 4; i++) {
                    int idx = tid + i * 256;
                    int row = idx >> 3;
                    int ch  = idx & 7;
                    uint64_t src = eh_g + (((uint64_t)(nn * BN + row)) * 32 + cc * 8 + ch) * 16;
                    uint32_t dst = dstb + row * 128 + ((ch ^ (row & 7)) << 4);
                    CP_ASYNC_16(dst, src);
                }
            }
            CP_COMMIT();
            sfill++; if (sfill == 3) sfill = 0;

            const uint32_t Bb = smem_u32 + SM_B + suse * 16384;
            suse++; if (suse == 3) suse = 0;
            const int aK = c * 8;
            #pragma unroll
            for (int ks = 0; ks < 4; ks++) {
                uint32_t a[2][4];
                #pragma unroll
                for (int i = 0; i < 2; i++) {
                    int row = wm * 32 + i * 16 + (lane & 15);
                    int ch = aK + ks * 2 + (lane >> 4);
                    LDMATRIX_X4(a[i], Ab + row * 512 + ((ch ^ (row & 7)) << 4));
                }
                #pragma unroll
                for (int jj = 0; jj < 4; jj++) {
                    uint32_t b[4];
                    int nloc = wn * 64 + jj * 16 + (lane & 7) + ((lane >> 4) << 3);
                    int ch = ks * 2 + ((lane >> 3) & 1);
                    LDMATRIX_X4(b, Bb + nloc * 128 + ((ch ^ (nloc & 7)) << 4));
                    #pragma unroll
                    for (int i = 0; i < 2; i++) {
                        MMA_16816_H(acc[i][jj * 2],     a[i], b[0], b[1]);
                        MMA_16816_H(acc[i][jj * 2 + 1], a[i], b[2], b[3]);
                    }
                }
            }
        }

        // ---- epilogue: unpack fp16 acc, paired stores, top-3 tracking ----
        const float* enb = g_enorm + n0 + wn * 64 + 2 * t;
        #pragma unroll
        for (int i = 0; i < 2; i++) {
            #pragma unroll
            for (int p = 0; p < 2; p++) {
                const int ii = i * 2 + p;
                const int grow = m0 + wm * 32 + i * 16 + p * 8 + g;
                const float xnr = xnv[ii];
                float* drow = out + D_OFF + (size_t)grow * NE + n0 + wn * 64;
                float prev_d1 = 0.0f;
                #pragma unroll
                for (int j = 0; j < 8; j++) {
                    float2 e2 = *(const float2*)(enb + j * 8);
                    float2 Sv = __half22float2(*(const __half2*)&acc[i][j][p]);
                    float d0 = fmaf(Sv.x, -4.8828125e-4f, xnr + e2.x);
                    float d1 = fmaf(Sv.y, -4.8828125e-4f, xnr + e2.y);
                    int cidx = n0 + wn * 64 + j * 8 + 2 * t;
                    if (d0 < mv3[ii]) {
                        if (d0 < mv2[ii]) {
                            mv3[ii]=mv2[ii]; mi3[ii]=mi2[ii];
                            if (d0 < mv1[ii]) { mv2[ii]=mv1[ii]; mi2[ii]=mi1[ii];
                                                mv1[ii]=d0; mi1[ii]=cidx; }
                            else { mv2[ii]=d0; mi2[ii]=cidx; }
                        } else { mv3[ii]=d0; mi3[ii]=cidx; }
                    }
                    if (d1 < mv3[ii]) {
                        if (d1 < mv2[ii]) {
                            mv3[ii]=mv2[ii]; mi3[ii]=mi2[ii];
                            if (d1 < mv1[ii]) { mv2[ii]=mv1[ii]; mi2[ii]=mi1[ii];
                                                mv1[ii]=d1; mi1[ii]=cidx+1; }
                            else { mv2[ii]=d1; mi2[ii]=cidx+1; }
                        } else { mv3[ii]=d1; mi3[ii]=cidx+1; }
                    }
                    float rot = __shfl_sync(0xffffffffu, d0, t + 1, 4);
                    if (t < 3) {
                        float2 v = make_float2(d1, rot);
                        __stcs((float2*)(drow + j * 8 + 2 * t + 1), v);
                    } else if (j > 0) {
                        float2 v = make_float2(prev_d1, rot);
                        __stcs((float2*)(drow + (j - 1) * 8 + 7), v);
                    }
                    if (t == 0 && j == 0) __stcs(drow, d0);
                    prev_d1 = d1;
                }
                if (t == 3) __stcs(drow + 63, prev_d1);
            }
        }
    }

    // dump per-lane top-3 candidates (8 lane-slots per row x 3 = 24 per row)
    #pragma unroll
    for (int ii = 0; ii < 4; ii++) {
        int grow = m0 + wm * 32 + (ii >> 1) * 16 + (ii & 1) * 8 + g;
        int base = grow * 24 + (wn * 4 + t) * 3;
        g_cand[base]     = mi1[ii];
        g_cand[base + 1] = mi2[ii];
        g_cand[base + 2] = mi3[ii];
    }
}

// ---------------------------------------------------------------------------
// Refine + gather + loss. One warp per row; each 16-lane HALF walks 12 of the
// 24 candidates (halved serial latency), cross-half combine at the end.
// Exact fp32 arithmetic; lexicographic (value, index) min.
// ---------------------------------------------------------------------------
__global__ void __launch_bounds__(256) vq_refine(const float* __restrict__ x,
                                                 const float* __restrict__ emb,
                                                 float* __restrict__ out) {
    __shared__ double sd[8];
    const int warp = threadIdx.x >> 5;
    const int lane = threadIdx.x & 31;
    const int hl = lane & 15;          // lane within half
    const int half = lane >> 4;        // 0 or 1
    const int row = blockIdx.x * 8 + warp;

    const float4* xp = (const float4*)(x + (size_t)row * DIM);
    float4 xq[4];
    #pragma unroll
    for (int i = 0; i < 4; i++) xq[i] = xp[hl + 16 * i];
    const float xn = g_xnorm[row];

    float bv = 3.4e38f;
    int bi = 0x7fffffff;
    #pragma unroll 3
    for (int it = 0; it < 12; it++) {
        const int idx = g_cand[row * 24 + half * 12 + it];
        const float4* ep = (const float4*)(emb + (size_t)idx * DIM);
        float s = 0.0f;
        #pragma unroll
        for (int i = 0; i < 4; i++) {
            float4 ev = __ldg(ep + hl + 16 * i);
            s = __fmaf_rn(xq[i].x, ev.x, s);
            s = __fmaf_rn(xq[i].y, ev.y, s);
            s = __fmaf_rn(xq[i].z, ev.z, s);
            s = __fmaf_rn(xq[i].w, ev.w, s);
        }
        #pragma unroll
        for (int o = 8; o > 0; o >>= 1)
            s += __shfl_xor_sync(0xffffffffu, s, o);
        float dv = __fmaf_rn(-2.0f, s, __fadd_rn(xn, g_enorm[idx]));
        if (dv < bv || (dv == bv && idx < bi)) { bv = dv; bi = idx; }
    }
    // cross-half combine
    {
        float ov = __shfl_xor_sync(0xffffffffu, bv, 16);
        int   oi = __shfl_xor_sync(0xffffffffu, bi, 16);
        if (ov < bv || (ov == bv && oi < bi)) { bv = ov; bi = oi; }
    }
    if (lane == 0) out[IDX_OFF + row] = (float)bi;

    // gather + x_q_ste + loss: half 0 only (16 lanes cover the row)
    if (half == 0) {
        const float4* ep = (const float4*)(emb + (size_t)bi * DIM);
        float4* oq = (float4*)(out + XQ_OFF + (size_t)row * DIM);
        float s2 = 0.0f;
        #pragma unroll
        for (int i = 0; i < 4; i++) {
            float4 ev = __ldg(ep + hl + 16 * i);
            float dx = ev.x - xq[i].x, dy = ev.y - xq[i].y;
            float dz = ev.z - xq[i].z, dw = ev.w - xq[i].w;
            float4 o;
            o.x = xq[i].x + dx; o.y = xq[i].y + dy;
            o.z = xq[i].z + dz; o.w = xq[i].w + dw;
            oq[hl + 16 * i] = o;
            s2 += dx*dx + dy*dy + dz*dz + dw*dw;
        }
        #pragma unroll
        for (int o = 8; o > 0; o >>= 1)
            s2 += __shfl_down_sync(0x0000ffffu, s2, o, 16);
        if (hl == 0) sd[warp] = (double)s2;
    }
    __syncthreads();
    if (threadIdx.x == 0) {
        double bs = 0.0;
        #pragma unroll
        for (int w = 0; w < 8; w++) bs += sd[w];
        atomicAdd(&g_losssum, bs);
    }
}

__global__ void vq_loss(float* __restrict__ out) {
    double mse = g_losssum / (double)(NROWS * DIM);
    out[LOSS_OFF] = (float)(1.25 * mse);
}

// ---------------------------------------------------------------------------
extern "C" void kernel_launch(void* const* d_in, const int* in_sizes, int n_in,
                              void* d_out, int out_size) {
    const float* x = (const float*)d_in[0];
    const float* emb = (const float*)d_in[1];
    float* out = (float*)d_out;
    (void)in_sizes; (void)n_in; (void)out_size;

    static bool attr_set = false;
    if (!attr_set) {
        cudaFuncSetAttribute(vq_main_mma, cudaFuncAttributeMaxDynamicSharedMemorySize,
                             SMEM_TOTAL);
        attr_set = true;
    }

    vq_prep<<<(NE + NROWS) / 8, 256>>>(x, emb);
    vq_main_mma<<<NROWS / BM, 256, SMEM_TOTAL>>>(out);
    vq_refine<<<NROWS / 8, 256>>>(x, emb, out);
    vq_loss<<<1, 1>>>(out);
}

// round 16
// speedup vs baseline: 1.2384x; 1.1914x over previous
#include <cuda_runtime.h>
#include <cuda_fp16.h>
#include <cstdint>

// Problem constants
#define NROWS 65536
#define DIM   256
#define NE    8192

// Output packing (float32, reference return order)
#define XQ_OFF   0ULL
#define LOSS_OFF 16777216ULL
#define IDX_OFF  16777217ULL
#define D_OFF    16842753ULL

// ---------------------------------------------------------------------------
// Device scratch
// ---------------------------------------------------------------------------
__device__ uint4 g_xh[NROWS * 32];   // fp16 x rows (32MB)
__device__ uint4 g_eh[NE * 32];      // fp16 emb rows, pre-scaled by 4096 (4MB)
__device__ __align__(16) float g_xnorm[NROWS];
__device__ __align__(16) float g_enorm[NE];
__device__ int    g_cand[NROWS * 12];   // 12 argmin candidates per row (3MB)
__device__ double g_losssum;

// ---------------------------------------------------------------------------
// helpers
// ---------------------------------------------------------------------------
__device__ __forceinline__ uint32_t smem_to_u32(const void* p) {
    uint32_t a;
    asm("{ .reg .u64 t; cvta.to.shared.u64 t, %1; cvt.u32.u64 %0, t; }"
        : "=r"(a) : "l"(p));
    return a;
}
__device__ __forceinline__ uint64_t to_global(const void* p) {
    uint64_t g;
    asm("cvta.to.global.u64 %0, %1;" : "=l"(g) : "l"(p));
    return g;
}
#define CP_ASYNC_16(dst, src) \
    asm volatile("cp.async.cg.shared.global [%0], [%1], 16;" :: "r"(dst), "l"(src))
#define CP_COMMIT() asm volatile("cp.async.commit_group;" ::: "memory")
#define CP_WAIT(n)  asm volatile("cp.async.wait_group %0;" :: "n"(n) : "memory")

#define LDMATRIX_X4(r, addr) \
    asm volatile("ldmatrix.sync.aligned.m8n8.x4.shared.b16 {%0,%1,%2,%3}, [%4];" \
        : "=r"((r)[0]), "=r"((r)[1]), "=r"((r)[2]), "=r"((r)[3]) : "r"(addr))

// fp16-accumulate HMMA: C fragment = 2 regs (half2 per 8-row block)
#define MMA_16816_H(c, a, b0, b1) \
    asm volatile("mma.sync.aligned.m16n8k16.row.col.f16.f16.f16.f16 " \
        "{%0,%1}, {%2,%3,%4,%5}, {%6,%7}, {%0,%1};" \
        : "+r"((c)[0]), "+r"((c)[1]) \
        : "r"((a)[0]), "r"((a)[1]), "r"((a)[2]), "r"((a)[3]), "r"(b0), "r"(b1))

__device__ __forceinline__ uint32_t pack_half2(__half lo, __half hi) {
    return (uint32_t)__half_as_ushort(lo) | ((uint32_t)__half_as_ushort(hi) << 16);
}

// ---------------------------------------------------------------------------
// prep+norms fused: one warp per row, single read of the source row.
// ---------------------------------------------------------------------------
__global__ void __launch_bounds__(256) vq_prep(const float* __restrict__ x,
                                               const float* __restrict__ emb) {
    if (blockIdx.x == 0 && threadIdx.x == 0) g_losssum = 0.0;
    int warp = threadIdx.x >> 5;
    int lane = threadIdx.x & 31;
    int row = blockIdx.x * 8 + warp;
    const float* src;
    float* ndst;
    uint4* qdst;
    float sc;
    if (row < NE) {
        src = emb + (size_t)row * DIM; ndst = g_enorm + row;
        qdst = g_eh + (size_t)row * 32; sc = 4096.0f;
    } else {
        int r = row - NE;
        if (r >= NROWS) return;
        src = x + (size_t)r * DIM; ndst = g_xnorm + r;
        qdst = g_xh + (size_t)r * 32; sc = 1.0f;
    }
    const float4* p = (const float4*)src;
    float4 v0 = p[lane * 2];
    float4 v1 = p[lane * 2 + 1];
    float s = v0.x*v0.x + v0.y*v0.y + v0.z*v0.z + v0.w*v0.w
            + v1.x*v1.x + v1.y*v1.y + v1.z*v1.z + v1.w*v1.w;
    #pragma unroll
    for (int o = 16; o > 0; o >>= 1)
        s += __shfl_down_sync(0xffffffffu, s, o);
    if (lane == 0) *ndst = s;

    __half h[8];
    h[0] = __float2half_rn(v0.x * sc); h[1] = __float2half_rn(v0.y * sc);
    h[2] = __float2half_rn(v0.z * sc); h[3] = __float2half_rn(v0.w * sc);
    h[4] = __float2half_rn(v1.x * sc); h[5] = __float2half_rn(v1.y * sc);
    h[6] = __float2half_rn(v1.z * sc); h[7] = __float2half_rn(v1.w * sc);
    uint4 u;
    u.x = pack_half2(h[0], h[1]); u.y = pack_half2(h[2], h[3]);
    u.z = pack_half2(h[4], h[5]); u.w = pack_half2(h[6], h[7]);
    qdst[lane] = u;
}

// ---------------------------------------------------------------------------
// Main HMMA kernel: grid = 512 m-blocks x 4 n-quarters (fine scheduling).
// Per CTA: BM=128, n-range 2048 cols (16 tiles of BN=128), fp16 acc,
// occupancy 2, paired float2 streaming stores, per-lane top-2 candidates,
// end-of-CTA merge to per-quarter top-3 (12 candidates/row globally).
// ---------------------------------------------------------------------------
#define BM 128
#define BN 128
#define NCH 4
#define NTQ 16                 // tiles per n-quarter
#define NQC (NTQ * NCH)        // 64 chunks per CTA
#define NSPAN 2048             // cols per quarter
#define SM_A 0
#define SM_B 65536
#define SMEM_TOTAL 114688      // 64KB A + 3*16KB B (x2 CTAs = 224KB)

__global__ void __launch_bounds__(256, 2) vq_main_mma(float* __restrict__ out) {
    extern __shared__ char smem[];
    const uint32_t smem_u32 = smem_to_u32(smem);
    const uint32_t Ab = smem_u32 + SM_A;
    const int tid = threadIdx.x;
    const int lane = tid & 31;
    const int wid = tid >> 5;
    const int wm = wid & 3;
    const int wn = wid >> 2;
    const int g = lane >> 2;
    const int t = lane & 3;
    const int m0 = (blockIdx.x >> 2) * BM;
    const int nqb = (blockIdx.x & 3) * NSPAN;   // quarter base column

    const uint64_t xh_g = to_global(g_xh);
    const uint64_t eh_g = to_global(g_eh);

    // A load: 128 rows x 32 16B-chunks
    #pragma unroll
    for (int i = 0; i < 16; i++) {
        int idx = tid + i * 256;
        int row = idx >> 5;
        int ch  = idx & 31;
        uint64_t src = xh_g + (((uint64_t)(m0 + row)) * 32 + ch) * 16;
        uint32_t dst = Ab + row * 512 + ((ch ^ (row & 7)) << 4);
        CP_ASYNC_16(dst, src);
    }
    CP_COMMIT();

    // B prologue: chunks 0,1 into stages 0,1
    #pragma unroll
    for (int p = 0; p < 2; p++) {
        uint32_t dstb = smem_u32 + SM_B + p * 16384;
        #pragma unroll
        for (int i = 0; i < 4; i++) {
            int idx = tid + i * 256;
            int row = idx >> 3;
            int ch  = idx & 7;
            uint64_t src = eh_g + (((uint64_t)(nqb + row)) * 32 + p * 8 + ch) * 16;
            uint32_t dst = dstb + row * 128 + ((ch ^ (row & 7)) << 4);
            CP_ASYNC_16(dst, src);
        }
        CP_COMMIT();
    }

    float xnv[4];
    #pragma unroll
    for (int ii = 0; ii < 4; ii++)
        xnv[ii] = g_xnorm[m0 + wm * 32 + (ii >> 1) * 16 + (ii & 1) * 8 + g];
    float mv1[4] = {3.4e38f, 3.4e38f, 3.4e38f, 3.4e38f};
    float mv2[4] = {3.4e38f, 3.4e38f, 3.4e38f, 3.4e38f};
    int   mi1[4] = {0, 0, 0, 0};
    int   mi2[4] = {0, 0, 0, 0};

    int q = 0;
    int sfill = 2, suse = 0;
    for (int n = 0; n < NTQ; n++) {
        const int n0 = nqb + n * BN;
        uint32_t acc[2][8][2];
        #pragma unroll
        for (int i = 0; i < 2; i++)
            #pragma unroll
            for (int j = 0; j < 8; j++) {
                acc[i][j][0] = 0u; acc[i][j][1] = 0u;
            }

        #pragma unroll
        for (int c = 0; c < NCH; c++, q++) {
            CP_WAIT(1);
            __syncthreads();

            int qi = q + 2;
            if (qi < NQC) {
                int nn = qi >> 2, cc = qi & 3;
                uint32_t dstb = smem_u32 + SM_B + sfill * 16384;
                #pragma unroll
                for (int i = 0; i < 4; i++) {
                    int idx = tid + i * 256;
                    int row = idx >> 3;
                    int ch  = idx & 7;
                    uint64_t src = eh_g + (((uint64_t)(nqb + nn * BN + row)) * 32 + cc * 8 + ch) * 16;
                    uint32_t dst = dstb + row * 128 + ((ch ^ (row & 7)) << 4);
                    CP_ASYNC_16(dst, src);
                }
            }
            CP_COMMIT();
            sfill++; if (sfill == 3) sfill = 0;

            const uint32_t Bb = smem_u32 + SM_B + suse * 16384;
            suse++; if (suse == 3) suse = 0;
            const int aK = c * 8;
            #pragma unroll
            for (int ks = 0; ks < 4; ks++) {
                uint32_t a[2][4];
                #pragma unroll
                for (int i = 0; i < 2; i++) {
                    int row = wm * 32 + i * 16 + (lane & 15);
                    int ch = aK + ks * 2 + (lane >> 4);
                    LDMATRIX_X4(a[i], Ab + row * 512 + ((ch ^ (row & 7)) << 4));
                }
                #pragma unroll
                for (int jj = 0; jj < 4; jj++) {
                    uint32_t b[4];
                    int nloc = wn * 64 + jj * 16 + (lane & 7) + ((lane >> 4) << 3);
                    int ch = ks * 2 + ((lane >> 3) & 1);
                    LDMATRIX_X4(b, Bb + nloc * 128 + ((ch ^ (nloc & 7)) << 4));
                    #pragma unroll
                    for (int i = 0; i < 2; i++) {
                        MMA_16816_H(acc[i][jj * 2],     a[i], b[0], b[1]);
                        MMA_16816_H(acc[i][jj * 2 + 1], a[i], b[2], b[3]);
                    }
                }
            }
        }

        // ---- epilogue: unpack fp16 acc, paired stores, top-2 tracking ----
        const float* enb = g_enorm + n0 + wn * 64 + 2 * t;
        #pragma unroll
        for (int i = 0; i < 2; i++) {
            #pragma unroll
            for (int p = 0; p < 2; p++) {
                const int ii = i * 2 + p;
                const int grow = m0 + wm * 32 + i * 16 + p * 8 + g;
                const float xnr = xnv[ii];
                float* drow = out + D_OFF + (size_t)grow * NE + n0 + wn * 64;
                float prev_d1 = 0.0f;
                #pragma unroll
                for (int j = 0; j < 8; j++) {
                    float2 e2 = *(const float2*)(enb + j * 8);
                    float2 Sv = __half22float2(*(const __half2*)&acc[i][j][p]);
                    float d0 = fmaf(Sv.x, -4.8828125e-4f, xnr + e2.x);
                    float d1 = fmaf(Sv.y, -4.8828125e-4f, xnr + e2.y);
                    int cidx = n0 + wn * 64 + j * 8 + 2 * t;
                    if (d0 < mv2[ii]) {
                        if (d0 < mv1[ii]) { mv2[ii]=mv1[ii]; mi2[ii]=mi1[ii];
                                            mv1[ii]=d0; mi1[ii]=cidx; }
                        else { mv2[ii]=d0; mi2[ii]=cidx; }
                    }
                    if (d1 < mv2[ii]) {
                        if (d1 < mv1[ii]) { mv2[ii]=mv1[ii]; mi2[ii]=mi1[ii];
                                            mv1[ii]=d1; mi1[ii]=cidx+1; }
                        else { mv2[ii]=d1; mi2[ii]=cidx+1; }
                    }
                    float rot = __shfl_sync(0xffffffffu, d0, t + 1, 4);
                    if (t < 3) {
                        float2 v = make_float2(d1, rot);
                        __stcs((float2*)(drow + j * 8 + 2 * t + 1), v);
                    } else if (j > 0) {
                        float2 v = make_float2(prev_d1, rot);
                        __stcs((float2*)(drow + (j - 1) * 8 + 7), v);
                    }
                    if (t == 0 && j == 0) __stcs(drow, d0);
                    prev_d1 = d1;
                }
                if (t == 3) __stcs(drow + 63, prev_d1);
            }
        }
    }

    // ---- merge per-lane top-2 -> per-quarter top-3 per row ----
    float* vv = (float*)(smem + SM_B);          // 128 rows x 16 floats (8KB)
    int*   iv = (int*)(smem + SM_B + 8192);     // 128 rows x 16 ints (8KB)
    __syncthreads();    // B stages fully consumed by all warps
    #pragma unroll
    for (int ii = 0; ii < 4; ii++) {
        int lrow = wm * 32 + (ii >> 1) * 16 + (ii & 1) * 8 + g;
        int slot = wn * 4 + t;
        vv[lrow * 16 + slot * 2]     = mv1[ii];
        vv[lrow * 16 + slot * 2 + 1] = mv2[ii];
        iv[lrow * 16 + slot * 2]     = mi1[ii];
        iv[lrow * 16 + slot * 2 + 1] = mi2[ii];
    }
    __syncthreads();
    if (tid < BM) {
        float b1 = 3.4e38f, b2 = 3.4e38f, b3 = 3.4e38f;
        int   j1 = 0x7fffffff, j2 = 0x7fffffff, j3 = 0x7fffffff;
        #pragma unroll
        for (int k = 0; k < 16; k++) {
            float v = vv[tid * 16 + k];
            int   ix = iv[tid * 16 + k];
            if (v < b3 || (v == b3 && ix < j3)) {
                if (v < b2 || (v == b2 && ix < j2)) {
                    b3 = b2; j3 = j2;
                    if (v < b1 || (v == b1 && ix < j1)) {
                        b2 = b1; j2 = j1; b1 = v; j1 = ix;
                    } else { b2 = v; j2 = ix; }
                } else { b3 = v; j3 = ix; }
            }
        }
        int base = (m0 + tid) * 12 + (blockIdx.x & 3) * 3;
        g_cand[base]     = j1;
        g_cand[base + 1] = j2;
        g_cand[base + 2] = j3;
    }
}

// ---------------------------------------------------------------------------
// Refine + gather + loss. One warp per row; each 16-lane half walks 6 of the
// 12 candidates; cross-half combine. Exact fp32 arithmetic.
// ---------------------------------------------------------------------------
__global__ void __launch_bounds__(256) vq_refine(const float* __restrict__ x,
                                                 const float* __restrict__ emb,
                                                 float* __restrict__ out) {
    __shared__ double sd[8];
    const int warp = threadIdx.x >> 5;
    const int lane = threadIdx.x & 31;
    const int hl = lane & 15;
    const int half = lane >> 4;
    const int row = blockIdx.x * 8 + warp;

    const float4* xp = (const float4*)(x + (size_t)row * DIM);
    float4 xq[4];
    #pragma unroll
    for (int i = 0; i < 4; i++) xq[i] = xp[hl + 16 * i];
    const float xn = g_xnorm[row];

    float bv = 3.4e38f;
    int bi = 0x7fffffff;
    #pragma unroll 3
    for (int it = 0; it < 6; it++) {
        const int idx = g_cand[row * 12 + half * 6 + it];
        const float4* ep = (const float4*)(emb + (size_t)idx * DIM);
        float s = 0.0f;
        #pragma unroll
        for (int i = 0; i < 4; i++) {
            float4 ev = __ldg(ep + hl + 16 * i);
            s = __fmaf_rn(xq[i].x, ev.x, s);
            s = __fmaf_rn(xq[i].y, ev.y, s);
            s = __fmaf_rn(xq[i].z, ev.z, s);
            s = __fmaf_rn(xq[i].w, ev.w, s);
        }
        #pragma unroll
        for (int o = 8; o > 0; o >>= 1)
            s += __shfl_xor_sync(0xffffffffu, s, o);
        float dv = __fmaf_rn(-2.0f, s, __fadd_rn(xn, g_enorm[idx]));
        if (dv < bv || (dv == bv && idx < bi)) { bv = dv; bi = idx; }
    }
    {
        float ov = __shfl_xor_sync(0xffffffffu, bv, 16);
        int   oi = __shfl_xor_sync(0xffffffffu, bi, 16);
        if (ov < bv || (ov == bv && oi < bi)) { bv = ov; bi = oi; }
    }
    if (lane == 0) out[IDX_OFF + row] = (float)bi;

    if (half == 0) {
        const float4* ep = (const float4*)(emb + (size_t)bi * DIM);
        float4* oq = (float4*)(out + XQ_OFF + (size_t)row * DIM);
        float s2 = 0.0f;
        #pragma unroll
        for (int i = 0; i < 4; i++) {
            float4 ev = __ldg(ep + hl + 16 * i);
            float dx = ev.x - xq[i].x, dy = ev.y - xq[i].y;
            float dz = ev.z - xq[i].z, dw = ev.w - xq[i].w;
            float4 o;
            o.x = xq[i].x + dx; o.y = xq[i].y + dy;
            o.z = xq[i].z + dz; o.w = xq[i].w + dw;
            oq[hl + 16 * i] = o;
            s2 += dx*dx + dy*dy + dz*dz + dw*dw;
        }
        #pragma unroll
        for (int o = 8; o > 0; o >>= 1)
            s2 += __shfl_down_sync(0x0000ffffu, s2, o, 16);
        if (hl == 0) sd[warp] = (double)s2;
    }
    __syncthreads();
    if (threadIdx.x == 0) {
        double bs = 0.0;
        #pragma unroll
        for (int w = 0; w < 8; w++) bs += sd[w];
        atomicAdd(&g_losssum, bs);
    }
}

__global__ void vq_loss(float* __restrict__ out) {
    double mse = g_losssum / (double)(NROWS * DIM);
    out[LOSS_OFF] = (float)(1.25 * mse);
}

// ---------------------------------------------------------------------------
extern "C" void kernel_launch(void* const* d_in, const int* in_sizes, int n_in,
                              void* d_out, int out_size) {
    const float* x = (const float*)d_in[0];
    const float* emb = (const float*)d_in[1];
    float* out = (float*)d_out;
    (void)in_sizes; (void)n_in; (void)out_size;

    static bool attr_set = false;
    if (!attr_set) {
        cudaFuncSetAttribute(vq_main_mma, cudaFuncAttributeMaxDynamicSharedMemorySize,
                             SMEM_TOTAL);
        attr_set = true;
    }

    vq_prep<<<(NE + NROWS) / 8, 256>>>(x, emb);
    vq_main_mma<<<(NROWS / BM) * 4, 256, SMEM_TOTAL>>>(out);
    vq_refine<<<NROWS / 8, 256>>>(x, emb, out);
    vq_loss<<<1, 1>>>(out);
}

// round 17
// speedup vs baseline: 1.2752x; 1.0297x over previous
#include <cuda_runtime.h>
#include <cuda_fp16.h>
#include <cstdint>

// Problem constants
#define NROWS 65536
#define DIM   256
#define NE    8192

// Output packing (float32, reference return order)
#define XQ_OFF   0ULL
#define LOSS_OFF 16777216ULL
#define IDX_OFF  16777217ULL
#define D_OFF    16842753ULL

// ---------------------------------------------------------------------------
// Device scratch
// ---------------------------------------------------------------------------
__device__ uint4 g_xh[NROWS * 32];   // fp16 x rows (32MB)
__device__ uint4 g_eh[NE * 32];      // fp16 emb rows, pre-scaled by 4096 (4MB)
__device__ __align__(16) float g_xnorm[NROWS];
__device__ __align__(16) float g_enorm[NE];
__device__ int    g_cand[NROWS * 12];   // 12 argmin candidates per row (3MB)
__device__ double g_losssum;
__device__ unsigned g_done;

// ---------------------------------------------------------------------------
// helpers
// ---------------------------------------------------------------------------
__device__ __forceinline__ uint32_t smem_to_u32(const void* p) {
    uint32_t a;
    asm("{ .reg .u64 t; cvta.to.shared.u64 t, %1; cvt.u32.u64 %0, t; }"
        : "=r"(a) : "l"(p));
    return a;
}
__device__ __forceinline__ uint64_t to_global(const void* p) {
    uint64_t g;
    asm("cvta.to.global.u64 %0, %1;" : "=l"(g) : "l"(p));
    return g;
}
#define CP_ASYNC_16(dst, src) \
    asm volatile("cp.async.cg.shared.global [%0], [%1], 16;" :: "r"(dst), "l"(src))
#define CP_COMMIT() asm volatile("cp.async.commit_group;" ::: "memory")
#define CP_WAIT(n)  asm volatile("cp.async.wait_group %0;" :: "n"(n) : "memory")

#define LDMATRIX_X4(r, addr) \
    asm volatile("ldmatrix.sync.aligned.m8n8.x4.shared.b16 {%0,%1,%2,%3}, [%4];" \
        : "=r"((r)[0]), "=r"((r)[1]), "=r"((r)[2]), "=r"((r)[3]) : "r"(addr))

// fp16-accumulate HMMA: C fragment = 2 regs (half2 per 8-row block)
#define MMA_16816_H(c, a, b0, b1) \
    asm volatile("mma.sync.aligned.m16n8k16.row.col.f16.f16.f16.f16 " \
        "{%0,%1}, {%2,%3,%4,%5}, {%6,%7}, {%0,%1};" \
        : "+r"((c)[0]), "+r"((c)[1]) \
        : "r"((a)[0]), "r"((a)[1]), "r"((a)[2]), "r"((a)[3]), "r"(b0), "r"(b1))

__device__ __forceinline__ uint32_t pack_half2(__half lo, __half hi) {
    return (uint32_t)__half_as_ushort(lo) | ((uint32_t)__half_as_ushort(hi) << 16);
}

// ---------------------------------------------------------------------------
// prep+norms fused: one warp per row, single read of the source row.
// ---------------------------------------------------------------------------
__global__ void __launch_bounds__(256) vq_prep(const float* __restrict__ x,
                                               const float* __restrict__ emb) {
    if (blockIdx.x == 0 && threadIdx.x == 0) { g_losssum = 0.0; g_done = 0u; }
    int warp = threadIdx.x >> 5;
    int lane = threadIdx.x & 31;
    int row = blockIdx.x * 8 + warp;
    const float* src;
    float* ndst;
    uint4* qdst;
    float sc;
    if (row < NE) {
        src = emb + (size_t)row * DIM; ndst = g_enorm + row;
        qdst = g_eh + (size_t)row * 32; sc = 4096.0f;
    } else {
        int r = row - NE;
        if (r >= NROWS) return;
        src = x + (size_t)r * DIM; ndst = g_xnorm + r;
        qdst = g_xh + (size_t)r * 32; sc = 1.0f;
    }
    const float4* p = (const float4*)src;
    float4 v0 = p[lane * 2];
    float4 v1 = p[lane * 2 + 1];
    float s = v0.x*v0.x + v0.y*v0.y + v0.z*v0.z + v0.w*v0.w
            + v1.x*v1.x + v1.y*v1.y + v1.z*v1.z + v1.w*v1.w;
    #pragma unroll
    for (int o = 16; o > 0; o >>= 1)
        s += __shfl_down_sync(0xffffffffu, s, o);
    if (lane == 0) *ndst = s;

    __half h[8];
    h[0] = __float2half_rn(v0.x * sc); h[1] = __float2half_rn(v0.y * sc);
    h[2] = __float2half_rn(v0.z * sc); h[3] = __float2half_rn(v0.w * sc);
    h[4] = __float2half_rn(v1.x * sc); h[5] = __float2half_rn(v1.y * sc);
    h[6] = __float2half_rn(v1.z * sc); h[7] = __float2half_rn(v1.w * sc);
    uint4 u;
    u.x = pack_half2(h[0], h[1]); u.y = pack_half2(h[2], h[3]);
    u.z = pack_half2(h[4], h[5]); u.w = pack_half2(h[6], h[7]);
    qdst[lane] = u;
}

// ---------------------------------------------------------------------------
// Main HMMA kernel: grid = 512 m-blocks x 4 n-quarters. Per CTA: BM=128,
// 16 BN=128 tiles, fp16 acc, occ 2, paired float2 streaming stores, hoisted
// e-norm loads, per-lane top-2 -> per-quarter top-3 candidate merge.
// ---------------------------------------------------------------------------
#define BM 128
#define BN 128
#define NCH 4
#define NTQ 16                 // tiles per n-quarter
#define NQC (NTQ * NCH)        // 64 chunks per CTA
#define NSPAN 2048             // cols per quarter
#define SM_A 0
#define SM_B 65536
#define SMEM_TOTAL 114688      // 64KB A + 3*16KB B (x2 CTAs = 224KB)

__global__ void __launch_bounds__(256, 2) vq_main_mma(float* __restrict__ out) {
    extern __shared__ char smem[];
    const uint32_t smem_u32 = smem_to_u32(smem);
    const uint32_t Ab = smem_u32 + SM_A;
    const int tid = threadIdx.x;
    const int lane = tid & 31;
    const int wid = tid >> 5;
    const int wm = wid & 3;
    const int wn = wid >> 2;
    const int g = lane >> 2;
    const int t = lane & 3;
    const int m0 = (blockIdx.x >> 2) * BM;
    const int nqb = (blockIdx.x & 3) * NSPAN;

    const uint64_t xh_g = to_global(g_xh);
    const uint64_t eh_g = to_global(g_eh);

    // A load: 128 rows x 32 16B-chunks
    #pragma unroll
    for (int i = 0; i < 16; i++) {
        int idx = tid + i * 256;
        int row = idx >> 5;
        int ch  = idx & 31;
        uint64_t src = xh_g + (((uint64_t)(m0 + row)) * 32 + ch) * 16;
        uint32_t dst = Ab + row * 512 + ((ch ^ (row & 7)) << 4);
        CP_ASYNC_16(dst, src);
    }
    CP_COMMIT();

    // B prologue: chunks 0,1 into stages 0,1
    #pragma unroll
    for (int p = 0; p < 2; p++) {
        uint32_t dstb = smem_u32 + SM_B + p * 16384;
        #pragma unroll
        for (int i = 0; i < 4; i++) {
            int idx = tid + i * 256;
            int row = idx >> 3;
            int ch  = idx & 7;
            uint64_t src = eh_g + (((uint64_t)(nqb + row)) * 32 + p * 8 + ch) * 16;
            uint32_t dst = dstb + row * 128 + ((ch ^ (row & 7)) << 4);
            CP_ASYNC_16(dst, src);
        }
        CP_COMMIT();
    }

    float xnv[4];
    #pragma unroll
    for (int ii = 0; ii < 4; ii++)
        xnv[ii] = g_xnorm[m0 + wm * 32 + (ii >> 1) * 16 + (ii & 1) * 8 + g];
    float mv1[4] = {3.4e38f, 3.4e38f, 3.4e38f, 3.4e38f};
    float mv2[4] = {3.4e38f, 3.4e38f, 3.4e38f, 3.4e38f};
    int   mi1[4] = {0, 0, 0, 0};
    int   mi2[4] = {0, 0, 0, 0};

    int q = 0;
    int sfill = 2, suse = 0;
    for (int n = 0; n < NTQ; n++) {
        const int n0 = nqb + n * BN;
        uint32_t acc[2][8][2];
        #pragma unroll
        for (int i = 0; i < 2; i++)
            #pragma unroll
            for (int j = 0; j < 8; j++) {
                acc[i][j][0] = 0u; acc[i][j][1] = 0u;
            }

        #pragma unroll
        for (int c = 0; c < NCH; c++, q++) {
            CP_WAIT(1);
            __syncthreads();

            int qi = q + 2;
            if (qi < NQC) {
                int nn = qi >> 2, cc = qi & 3;
                uint32_t dstb = smem_u32 + SM_B + sfill * 16384;
                #pragma unroll
                for (int i = 0; i < 4; i++) {
                    int idx = tid + i * 256;
                    int row = idx >> 3;
                    int ch  = idx & 7;
                    uint64_t src = eh_g + (((uint64_t)(nqb + nn * BN + row)) * 32 + cc * 8 + ch) * 16;
                    uint32_t dst = dstb + row * 128 + ((ch ^ (row & 7)) << 4);
                    CP_ASYNC_16(dst, src);
                }
            }
            CP_COMMIT();
            sfill++; if (sfill == 3) sfill = 0;

            const uint32_t Bb = smem_u32 + SM_B + suse * 16384;
            suse++; if (suse == 3) suse = 0;
            const int aK = c * 8;
            #pragma unroll
            for (int ks = 0; ks < 4; ks++) {
                uint32_t a[2][4];
                #pragma unroll
                for (int i = 0; i < 2; i++) {
                    int row = wm * 32 + i * 16 + (lane & 15);
                    int ch = aK + ks * 2 + (lane >> 4);
                    LDMATRIX_X4(a[i], Ab + row * 512 + ((ch ^ (row & 7)) << 4));
                }
                #pragma unroll
                for (int jj = 0; jj < 4; jj++) {
                    uint32_t b[4];
                    int nloc = wn * 64 + jj * 16 + (lane & 7) + ((lane >> 4) << 3);
                    int ch = ks * 2 + ((lane >> 3) & 1);
                    LDMATRIX_X4(b, Bb + nloc * 128 + ((ch ^ (nloc & 7)) << 4));
                    #pragma unroll
                    for (int i = 0; i < 2; i++) {
                        MMA_16816_H(acc[i][jj * 2],     a[i], b[0], b[1]);
                        MMA_16816_H(acc[i][jj * 2 + 1], a[i], b[2], b[3]);
                    }
                }
            }
        }

        // ---- epilogue: hoisted e-norm loads, paired stores, top-2 tracking ----
        float2 e2v[8];
        {
            const float* enb = g_enorm + n0 + wn * 64 + 2 * t;
            #pragma unroll
            for (int j = 0; j < 8; j++)
                e2v[j] = *(const float2*)(enb + j * 8);
        }
        #pragma unroll
        for (int i = 0; i < 2; i++) {
            #pragma unroll
            for (int p = 0; p < 2; p++) {
                const int ii = i * 2 + p;
                const int grow = m0 + wm * 32 + i * 16 + p * 8 + g;
                const float xnr = xnv[ii];
                float* drow = out + D_OFF + (size_t)grow * NE + n0 + wn * 64;
                float prev_d1 = 0.0f;
                #pragma unroll
                for (int j = 0; j < 8; j++) {
                    float2 Sv = __half22float2(*(const __half2*)&acc[i][j][p]);
                    float d0 = fmaf(Sv.x, -4.8828125e-4f, xnr + e2v[j].x);
                    float d1 = fmaf(Sv.y, -4.8828125e-4f, xnr + e2v[j].y);
                    int cidx = n0 + wn * 64 + j * 8 + 2 * t;
                    if (d0 < mv2[ii]) {
                        if (d0 < mv1[ii]) { mv2[ii]=mv1[ii]; mi2[ii]=mi1[ii];
                                            mv1[ii]=d0; mi1[ii]=cidx; }
                        else { mv2[ii]=d0; mi2[ii]=cidx; }
                    }
                    if (d1 < mv2[ii]) {
                        if (d1 < mv1[ii]) { mv2[ii]=mv1[ii]; mi2[ii]=mi1[ii];
                                            mv1[ii]=d1; mi1[ii]=cidx+1; }
                        else { mv2[ii]=d1; mi2[ii]=cidx+1; }
                    }
                    float rot = __shfl_sync(0xffffffffu, d0, t + 1, 4);
                    if (t < 3) {
                        float2 v = make_float2(d1, rot);
                        __stcs((float2*)(drow + j * 8 + 2 * t + 1), v);
                    } else if (j > 0) {
                        float2 v = make_float2(prev_d1, rot);
                        __stcs((float2*)(drow + (j - 1) * 8 + 7), v);
                    }
                    if (t == 0 && j == 0) __stcs(drow, d0);
                    prev_d1 = d1;
                }
                if (t == 3) __stcs(drow + 63, prev_d1);
            }
        }
    }

    // ---- merge per-lane top-2 -> per-quarter top-3 per row ----
    float* vv = (float*)(smem + SM_B);          // 128 rows x 16 floats (8KB)
    int*   iv = (int*)(smem + SM_B + 8192);     // 128 rows x 16 ints (8KB)
    __syncthreads();
    #pragma unroll
    for (int ii = 0; ii < 4; ii++) {
        int lrow = wm * 32 + (ii >> 1) * 16 + (ii & 1) * 8 + g;
        int slot = wn * 4 + t;
        vv[lrow * 16 + slot * 2]     = mv1[ii];
        vv[lrow * 16 + slot * 2 + 1] = mv2[ii];
        iv[lrow * 16 + slot * 2]     = mi1[ii];
        iv[lrow * 16 + slot * 2 + 1] = mi2[ii];
    }
    __syncthreads();
    if (tid < BM) {
        float b1 = 3.4e38f, b2 = 3.4e38f, b3 = 3.4e38f;
        int   j1 = 0x7fffffff, j2 = 0x7fffffff, j3 = 0x7fffffff;
        #pragma unroll
        for (int k = 0; k < 16; k++) {
            float v = vv[tid * 16 + k];
            int   ix = iv[tid * 16 + k];
            if (v < b3 || (v == b3 && ix < j3)) {
                if (v < b2 || (v == b2 && ix < j2)) {
                    b3 = b2; j3 = j2;
                    if (v < b1 || (v == b1 && ix < j1)) {
                        b2 = b1; j2 = j1; b1 = v; j1 = ix;
                    } else { b2 = v; j2 = ix; }
                } else { b3 = v; j3 = ix; }
            }
        }
        int base = (m0 + tid) * 12 + (blockIdx.x & 3) * 3;
        g_cand[base]     = j1;
        g_cand[base + 1] = j2;
        g_cand[base + 2] = j3;
    }
}

// ---------------------------------------------------------------------------
// Refine + gather + loss (+ final loss write via last-block ticket).
// One warp per row; each 16-lane half walks 6 of 12 candidates.
// ---------------------------------------------------------------------------
__global__ void __launch_bounds__(256) vq_refine(const float* __restrict__ x,
                                                 const float* __restrict__ emb,
                                                 float* __restrict__ out) {
    __shared__ double sd[8];
    const int warp = threadIdx.x >> 5;
    const int lane = threadIdx.x & 31;
    const int hl = lane & 15;
    const int half = lane >> 4;
    const int row = blockIdx.x * 8 + warp;

    const float4* xp = (const float4*)(x + (size_t)row * DIM);
    float4 xq[4];
    #pragma unroll
    for (int i = 0; i < 4; i++) xq[i] = xp[hl + 16 * i];
    const float xn = g_xnorm[row];

    float bv = 3.4e38f;
    int bi = 0x7fffffff;
    #pragma unroll 3
    for (int it = 0; it < 6; it++) {
        const int idx = g_cand[row * 12 + half * 6 + it];
        const float4* ep = (const float4*)(emb + (size_t)idx * DIM);
        float s = 0.0f;
        #pragma unroll
        for (int i = 0; i < 4; i++) {
            float4 ev = __ldg(ep + hl + 16 * i);
            s = __fmaf_rn(xq[i].x, ev.x, s);
            s = __fmaf_rn(xq[i].y, ev.y, s);
            s = __fmaf_rn(xq[i].z, ev.z, s);
            s = __fmaf_rn(xq[i].w, ev.w, s);
        }
        #pragma unroll
        for (int o = 8; o > 0; o >>= 1)
            s += __shfl_xor_sync(0xffffffffu, s, o);
        float dv = __fmaf_rn(-2.0f, s, __fadd_rn(xn, g_enorm[idx]));
        if (dv < bv || (dv == bv && idx < bi)) { bv = dv; bi = idx; }
    }
    {
        float ov = __shfl_xor_sync(0xffffffffu, bv, 16);
        int   oi = __shfl_xor_sync(0xffffffffu, bi, 16);
        if (ov < bv || (ov == bv && oi < bi)) { bv = ov; bi = oi; }
    }
    if (lane == 0) out[IDX_OFF + row] = (float)bi;

    if (half == 0) {
        const float4* ep = (const float4*)(emb + (size_t)bi * DIM);
        float4* oq = (float4*)(out + XQ_OFF + (size_t)row * DIM);
        float s2 = 0.0f;
        #pragma unroll
        for (int i = 0; i < 4; i++) {
            float4 ev = __ldg(ep + hl + 16 * i);
            float dx = ev.x - xq[i].x, dy = ev.y - xq[i].y;
            float dz = ev.z - xq[i].z, dw = ev.w - xq[i].w;
            float4 o;
            o.x = xq[i].x + dx; o.y = xq[i].y + dy;
            o.z = xq[i].z + dz; o.w = xq[i].w + dw;
            oq[hl + 16 * i] = o;
            s2 += dx*dx + dy*dy + dz*dz + dw*dw;
        }
        #pragma unroll
        for (int o = 8; o > 0; o >>= 1)
            s2 += __shfl_down_sync(0x0000ffffu, s2, o, 16);
        if (hl == 0) sd[warp] = (double)s2;
    }
    __syncthreads();
    if (threadIdx.x == 0) {
        double bs = 0.0;
        #pragma unroll
        for (int w = 0; w < 8; w++) bs += sd[w];
        atomicAdd(&g_losssum, bs);
        __threadfence();
        unsigned ticket = atomicAdd(&g_done, 1u);
        if (ticket == gridDim.x - 1) {
            g_done = 0u;
            double mse = g_losssum / (double)(NROWS * DIM);
            out[LOSS_OFF] = (float)(1.25 * mse);
        }
    }
}

// ---------------------------------------------------------------------------
extern "C" void kernel_launch(void* const* d_in, const int* in_sizes, int n_in,
                              void* d_out, int out_size) {
    const float* x = (const float*)d_in[0];
    const float* emb = (const float*)d_in[1];
    float* out = (float*)d_out;
    (void)in_sizes; (void)n_in; (void)out_size;

    static bool attr_set = false;
    if (!attr_set) {
        cudaFuncSetAttribute(vq_main_mma, cudaFuncAttributeMaxDynamicSharedMemorySize,
                             SMEM_TOTAL);
        attr_set = true;
    }

    vq_prep<<<(NE + NROWS) / 8, 256>>>(x, emb);
    vq_main_mma<<<(NROWS / BM) * 4, 256, SMEM_TOTAL>>>(out);
    vq_refine<<<NROWS / 8, 256>>>(x, emb, out);
}